// round 1
// baseline (speedup 1.0000x reference)
#include <cuda_runtime.h>
#include <math.h>

// ---------------------------------------------------------------------------
// Problem constants
// ---------------------------------------------------------------------------
#define BATCH   2
#define SEQ     2048
#define MTOT    4096          // BATCH * SEQ
#define DIMM    2048
#define NH      16
#define DHD     128
#define DRP     64
#define DQK     192           // DHD + DRP
#define QCOLS   3072          // NH * DQK
#define KVCOLS  4096          // NH * 2 * DHD
#define LATENT  512

// ---------------------------------------------------------------------------
// Scratch (device globals; no runtime allocation allowed)
// ---------------------------------------------------------------------------
__device__ float g_q  [(size_t)MTOT * QCOLS];    // q (nope|rope), rope applied in place
__device__ float g_ckv[(size_t)MTOT * LATENT];
__device__ float g_kr [(size_t)MTOT * DRP];      // k_rope, rope applied in place
__device__ float g_kv [(size_t)MTOT * KVCOLS];   // per head: [k_nope(128) | v(128)]
__device__ float g_ao [(size_t)MTOT * DIMM];     // attention output (B,S,H*DH)

// ---------------------------------------------------------------------------
// SGEMM: C[M,N] = A[M,K] @ B[K,N], row-major, fp32.
// BM=BN=128, BK=16, 256 threads, 8x8 per-thread tile.
// M % 128 == 0, K % 16 == 0 assumed (true for all calls); N guarded.
// ---------------------------------------------------------------------------
#define BM 128
#define BN 128
#define BKK 16

__global__ __launch_bounds__(256) void sgemm_kernel(
    const float* __restrict__ A, const float* __restrict__ B,
    float* __restrict__ C, int M, int N, int K)
{
    __shared__ float As[BKK][BM];   // transposed A tile
    __shared__ float Bs[BKK][BN];

    const int tid  = threadIdx.x;
    const int bm   = blockIdx.y * BM;
    const int bn   = blockIdx.x * BN;

    const int arow = tid >> 2;          // 0..63
    const int acol = (tid & 3) << 2;    // 0,4,8,12
    const int brow = tid >> 5;          // 0..7
    const int bcol = (tid & 31) << 2;   // 0..124

    const int ty = tid >> 4;            // 0..15
    const int tx = tid & 15;            // 0..15

    float acc[8][8];
    #pragma unroll
    for (int i = 0; i < 8; i++)
        #pragma unroll
        for (int j = 0; j < 8; j++) acc[i][j] = 0.0f;

    for (int k0 = 0; k0 < K; k0 += BKK) {
        // Load A tile (128 x 16), store transposed
        float4 a0 = *(const float4*)(A + (size_t)(bm + arow)      * K + k0 + acol);
        float4 a1 = *(const float4*)(A + (size_t)(bm + arow + 64) * K + k0 + acol);
        As[acol + 0][arow] = a0.x; As[acol + 1][arow] = a0.y;
        As[acol + 2][arow] = a0.z; As[acol + 3][arow] = a0.w;
        As[acol + 0][arow + 64] = a1.x; As[acol + 1][arow + 64] = a1.y;
        As[acol + 2][arow + 64] = a1.z; As[acol + 3][arow + 64] = a1.w;

        // Load B tile (16 x 128) with N guard
        if (bn + bcol + 3 < N) {
            *(float4*)&Bs[brow][bcol]     = *(const float4*)(B + (size_t)(k0 + brow)     * N + bn + bcol);
            *(float4*)&Bs[brow + 8][bcol] = *(const float4*)(B + (size_t)(k0 + brow + 8) * N + bn + bcol);
        } else {
            #pragma unroll
            for (int e = 0; e < 4; e++) {
                int c = bn + bcol + e;
                Bs[brow][bcol + e]     = (c < N) ? B[(size_t)(k0 + brow)     * N + c] : 0.0f;
                Bs[brow + 8][bcol + e] = (c < N) ? B[(size_t)(k0 + brow + 8) * N + c] : 0.0f;
            }
        }
        __syncthreads();

        #pragma unroll
        for (int k = 0; k < BKK; k++) {
            float a[8], b[8];
            *(float4*)&a[0] = *(float4*)&As[k][ty * 8];
            *(float4*)&a[4] = *(float4*)&As[k][ty * 8 + 4];
            *(float4*)&b[0] = *(float4*)&Bs[k][tx * 8];
            *(float4*)&b[4] = *(float4*)&Bs[k][tx * 8 + 4];
            #pragma unroll
            for (int i = 0; i < 8; i++)
                #pragma unroll
                for (int j = 0; j < 8; j++)
                    acc[i][j] = fmaf(a[i], b[j], acc[i][j]);
        }
        __syncthreads();
    }

    #pragma unroll
    for (int i = 0; i < 8; i++) {
        size_t row = (size_t)(bm + ty * 8 + i);
        #pragma unroll
        for (int j = 0; j < 8; j++) {
            int col = bn + tx * 8 + j;
            if (col < N) C[row * N + col] = acc[i][j];
        }
    }
}

// ---------------------------------------------------------------------------
// RoPE kernels (in place). Pair (j, j+32) handled by one thread.
// Mimics reference fp32 path: inv_freq correctly-rounded fp32, angle = fp32(s*inv).
// ---------------------------------------------------------------------------
__global__ void rope_q_kernel(float* __restrict__ q)
{
    int idx = blockIdx.x * blockDim.x + threadIdx.x;
    if (idx >= MTOT * NH * 32) return;
    int j   = idx & 31;
    int h   = (idx >> 5) & (NH - 1);
    int row = idx >> 9;
    int s   = row & (SEQ - 1);

    double invd = exp(-(double)j * (9.210340371976184 / 32.0)); // ln(10000)/32
    float inv = (float)invd;
    float ang = (float)s * inv;
    float sn, cs;
    sincosf(ang, &sn, &cs);

    float* p = q + (size_t)row * QCOLS + h * DQK + DHD;
    float x1 = p[j], x2 = p[j + 32];
    p[j]      = x1 * cs - x2 * sn;
    p[j + 32] = x2 * cs + x1 * sn;
}

__global__ void rope_k_kernel(float* __restrict__ kr)
{
    int idx = blockIdx.x * blockDim.x + threadIdx.x;
    if (idx >= MTOT * 32) return;
    int j   = idx & 31;
    int row = idx >> 5;
    int s   = row & (SEQ - 1);

    double invd = exp(-(double)j * (9.210340371976184 / 32.0));
    float inv = (float)invd;
    float ang = (float)s * inv;
    float sn, cs;
    sincosf(ang, &sn, &cs);

    float* p = kr + (size_t)row * DRP;
    float x1 = p[j], x2 = p[j + 32];
    p[j]      = x1 * cs - x2 * sn;
    p[j + 32] = x2 * cs + x1 * sn;
}

// ---------------------------------------------------------------------------
// Flash attention: BQ = BK = 64, d_qk = 192, d_v = 128, causal.
// 256 threads. Per-thread: 4x4 score tile, 4x8 O tile.
// smem strides padded: Q/K 193, V 132, S 65.
// ---------------------------------------------------------------------------
#define QKS 193
#define VSS 132
#define SSS 65
#define ATTN_SMEM_FLOATS (64*QKS + 64*QKS + 64*VSS + 64*SSS + 3*64)
#define ATTN_SMEM_BYTES  (ATTN_SMEM_FLOATS * 4)

__global__ __launch_bounds__(256) void attn_kernel(
    const float* __restrict__ gq, const float* __restrict__ gkv,
    const float* __restrict__ gkr, float* __restrict__ gao)
{
    extern __shared__ float sm[];
    float* sQ  = sm;
    float* sK  = sQ + 64 * QKS;
    float* sV  = sK + 64 * QKS;
    float* sS  = sV + 64 * VSS;
    float* sMx = sS + 64 * SSS;
    float* sL  = sMx + 64;
    float* sC  = sL + 64;

    const int q0 = blockIdx.x * 64;
    const int h  = blockIdx.y;
    const int b  = blockIdx.z;
    const int t  = threadIdx.x;

    const int r0  = (t >> 4) * 4;   // score/O row base
    const int cs0 = (t & 15) * 4;   // score col base
    const int co0 = (t & 15) * 8;   // O col base

    // Load Q tile (d=192 contiguous in g_q per (row, head))
    for (int i = t; i < 64 * DQK; i += 256) {
        int r = i / DQK, d = i - r * DQK;
        sQ[r * QKS + d] = gq[(size_t)(b * SEQ + q0 + r) * QCOLS + h * DQK + d];
    }
    if (t < 64) { sMx[t] = -INFINITY; sL[t] = 0.0f; }

    float o[4][8];
    #pragma unroll
    for (int i = 0; i < 4; i++)
        #pragma unroll
        for (int j = 0; j < 8; j++) o[i][j] = 0.0f;

    const int ntiles = (q0 >> 6) + 1;
    const float scale = 0.07216878364870323f;  // 1/sqrt(192)

    for (int kt = 0; kt < ntiles; kt++) {
        const int k0 = kt << 6;
        __syncthreads();  // protect sK/sV/sS from previous iteration readers

        // Load K tile: [k_nope(128) | roped k_rope(64, head-broadcast)]
        for (int i = t; i < 64 * DQK; i += 256) {
            int r = i / DQK, d = i - r * DQK;
            size_t gr = (size_t)(b * SEQ + k0 + r);
            sK[r * QKS + d] = (d < DHD) ? gkv[gr * KVCOLS + h * 256 + d]
                                        : gkr[gr * DRP + (d - DHD)];
        }
        // Load V tile
        for (int i = t; i < 64 * DHD; i += 256) {
            int r = i >> 7, d = i & 127;
            sV[r * VSS + d] = gkv[(size_t)(b * SEQ + k0 + r) * KVCOLS + h * 256 + DHD + d];
        }
        __syncthreads();

        // S = Q K^T  (4x4 per thread over d=192)
        float sacc[4][4];
        #pragma unroll
        for (int i = 0; i < 4; i++)
            #pragma unroll
            for (int j = 0; j < 4; j++) sacc[i][j] = 0.0f;

        #pragma unroll 4
        for (int d = 0; d < DQK; d++) {
            float a[4], bb[4];
            #pragma unroll
            for (int i = 0; i < 4; i++) a[i]  = sQ[(r0 + i) * QKS + d];
            #pragma unroll
            for (int j = 0; j < 4; j++) bb[j] = sK[(cs0 + j) * QKS + d];
            #pragma unroll
            for (int i = 0; i < 4; i++)
                #pragma unroll
                for (int j = 0; j < 4; j++)
                    sacc[i][j] = fmaf(a[i], bb[j], sacc[i][j]);
        }

        const bool diag = (k0 == q0);
        #pragma unroll
        for (int i = 0; i < 4; i++)
            #pragma unroll
            for (int j = 0; j < 4; j++) {
                float s = sacc[i][j] * scale;
                if (diag && (cs0 + j > r0 + i)) s = -INFINITY;
                sS[(r0 + i) * SSS + cs0 + j] = s;
            }
        __syncthreads();

        // Online softmax (one thread per row)
        if (t < 64) {
            float mo = sMx[t], mx = mo;
            #pragma unroll 8
            for (int j = 0; j < 64; j++) mx = fmaxf(mx, sS[t * SSS + j]);
            float c = __expf(mo - mx);       // 0 on first tile (mo = -inf)
            float l = sL[t] * c;
            #pragma unroll 8
            for (int j = 0; j < 64; j++) {
                float p = __expf(sS[t * SSS + j] - mx);
                sS[t * SSS + j] = p;
                l += p;
            }
            sMx[t] = mx; sL[t] = l; sC[t] = c;
        }
        __syncthreads();

        // Rescale O and accumulate P @ V
        float cc[4];
        #pragma unroll
        for (int i = 0; i < 4; i++) cc[i] = sC[r0 + i];
        #pragma unroll
        for (int i = 0; i < 4; i++)
            #pragma unroll
            for (int j = 0; j < 8; j++) o[i][j] *= cc[i];

        #pragma unroll 4
        for (int k = 0; k < 64; k++) {
            float p[4];
            #pragma unroll
            for (int i = 0; i < 4; i++) p[i] = sS[(r0 + i) * SSS + k];
            float4 v0 = *(float4*)&sV[k * VSS + co0];
            float4 v1 = *(float4*)&sV[k * VSS + co0 + 4];
            #pragma unroll
            for (int i = 0; i < 4; i++) {
                o[i][0] = fmaf(p[i], v0.x, o[i][0]);
                o[i][1] = fmaf(p[i], v0.y, o[i][1]);
                o[i][2] = fmaf(p[i], v0.z, o[i][2]);
                o[i][3] = fmaf(p[i], v0.w, o[i][3]);
                o[i][4] = fmaf(p[i], v1.x, o[i][4]);
                o[i][5] = fmaf(p[i], v1.y, o[i][5]);
                o[i][6] = fmaf(p[i], v1.z, o[i][6]);
                o[i][7] = fmaf(p[i], v1.w, o[i][7]);
            }
        }
    }

    // Epilogue: normalize and write
    #pragma unroll
    for (int i = 0; i < 4; i++) {
        float inv = 1.0f / sL[r0 + i];
        size_t row = (size_t)(b * SEQ + q0 + r0 + i);
        #pragma unroll
        for (int j = 0; j < 8; j++)
            gao[row * DIMM + h * DHD + co0 + j] = o[i][j] * inv;
    }
}

// ---------------------------------------------------------------------------
// Launch
// ---------------------------------------------------------------------------
extern "C" void kernel_launch(void* const* d_in, const int* in_sizes, int n_in,
                              void* d_out, int out_size)
{
    const float* x    = (const float*)d_in[0];
    const float* Wq   = (const float*)d_in[1];
    const float* Wdkv = (const float*)d_in[2];
    const float* Wkr  = (const float*)d_in[3];
    const float* Wukv = (const float*)d_in[4];
    const float* Wo   = (const float*)d_in[5];
    float* out = (float*)d_out;

    float *q, *ckv, *kr, *kv, *ao;
    cudaGetSymbolAddress((void**)&q,   g_q);
    cudaGetSymbolAddress((void**)&ckv, g_ckv);
    cudaGetSymbolAddress((void**)&kr,  g_kr);
    cudaGetSymbolAddress((void**)&kv,  g_kv);
    cudaGetSymbolAddress((void**)&ao,  g_ao);

    cudaFuncSetAttribute(attn_kernel,
                         cudaFuncAttributeMaxDynamicSharedMemorySize,
                         ATTN_SMEM_BYTES);

    // Projections
    sgemm_kernel<<<dim3(QCOLS / BN, MTOT / BM), 256>>>(x, Wq,   q,   MTOT, QCOLS,  DIMM);
    sgemm_kernel<<<dim3(LATENT / BN, MTOT / BM), 256>>>(x, Wdkv, ckv, MTOT, LATENT, DIMM);
    sgemm_kernel<<<dim3(1, MTOT / BM), 256>>>(x, Wkr, kr, MTOT, DRP, DIMM);
    sgemm_kernel<<<dim3(KVCOLS / BN, MTOT / BM), 256>>>(ckv, Wukv, kv, MTOT, KVCOLS, LATENT);

    // RoPE (in place)
    rope_q_kernel<<<(MTOT * NH * 32 + 255) / 256, 256>>>(q);
    rope_k_kernel<<<(MTOT * 32 + 255) / 256, 256>>>(kr);

    // Attention
    attn_kernel<<<dim3(SEQ / 64, NH, BATCH), 256, ATTN_SMEM_BYTES>>>(q, kv, kr, ao);

    // Output projection
    sgemm_kernel<<<dim3(DIMM / BN, MTOT / BM), 256>>>(ao, Wo, out, MTOT, DIMM, DIMM);
}

// round 5
// speedup vs baseline: 2.1011x; 2.1011x over previous
#include <cuda_runtime.h>
#include <math.h>

// ---------------------------------------------------------------------------
// Problem constants
// ---------------------------------------------------------------------------
#define BATCH   2
#define SEQ     2048
#define MTOT    4096          // BATCH * SEQ
#define DIMM    2048
#define NH      16
#define DHD     128
#define DRP     64
#define DQK     192           // DHD + DRP
#define QCOLS   3072          // NH * DQK
#define KVCOLS  4096          // NH * 2 * DHD
#define LATENT  512

// ---------------------------------------------------------------------------
// Scratch (device globals; no runtime allocation allowed)
// ---------------------------------------------------------------------------
__device__ float g_q  [(size_t)MTOT * QCOLS];    // q (nope|rope), rope in place
__device__ float g_ckv[(size_t)MTOT * LATENT];
__device__ float g_kr [(size_t)MTOT * DRP];      // k_rope, rope in place
__device__ float g_kv [(size_t)MTOT * KVCOLS];   // per head: [k_nope(128) | v(128)]
__device__ float g_ao [(size_t)MTOT * DIMM];     // attention output (B,S,H*DH)

// tf32-prerounded operand copies
__device__ float g_xr   [(size_t)MTOT * DIMM];
__device__ float g_Wqr  [(size_t)DIMM * QCOLS];
__device__ float g_Wdkvr[(size_t)DIMM * LATENT];
__device__ float g_Wkrr [(size_t)DIMM * DRP];
__device__ float g_Wukvr[(size_t)LATENT * KVCOLS];
__device__ float g_Wor  [(size_t)DIMM * DIMM];

// ---------------------------------------------------------------------------
// tf32 round-to-nearest (cvt.rna) helpers
// ---------------------------------------------------------------------------
__device__ __forceinline__ float tf32_rna(float x)
{
    unsigned u;
    asm("cvt.rna.tf32.f32 %0, %1;" : "=r"(u) : "f"(x));
    return __uint_as_float(u);
}
__device__ __forceinline__ unsigned tf32_rna_u(float x)
{
    unsigned u;
    asm("cvt.rna.tf32.f32 %0, %1;" : "=r"(u) : "f"(x));
    return u;
}

__global__ void tf32_round_kernel(const float* __restrict__ in,
                                  float* __restrict__ out, int n4)
{
    int i = blockIdx.x * blockDim.x + threadIdx.x;
    int stride = gridDim.x * blockDim.x;
    for (; i < n4; i += stride) {
        float4 v = ((const float4*)in)[i];
        v.x = tf32_rna(v.x); v.y = tf32_rna(v.y);
        v.z = tf32_rna(v.z); v.w = tf32_rna(v.w);
        ((float4*)out)[i] = v;
    }
}

// ---------------------------------------------------------------------------
// tf32 tensor-core GEMM: C[M,N] = A[M,K] @ B[K,N], row-major fp32 (tf32-
// prerounded inputs). BM=BN=128, BK=32, 256 threads (8 warps, 64x32 warp
// tile), mma.sync.m16n8k8, cp.async double-buffered smem.
// ---------------------------------------------------------------------------
#define GBM 128
#define GBN 128
#define GBK 32
#define ASTR 36
#define BSTR 132
#define STAGE_A (GBM * ASTR)
#define STAGE_B (GBK * BSTR)
#define STAGE_FLOATS (STAGE_A + STAGE_B)
#define GEMM_SMEM_BYTES (2 * STAGE_FLOATS * 4)

__device__ __forceinline__ unsigned smem_u32(const void* p)
{
    unsigned a;
    asm("{ .reg .u64 t; cvta.to.shared.u64 t, %1; cvt.u32.u64 %0, t; }"
        : "=r"(a) : "l"(p));
    return a;
}

#define MMA_TF32(acc, a0, a1, a2, a3, b0, b1)                                 \
    asm volatile(                                                             \
        "mma.sync.aligned.m16n8k8.row.col.f32.tf32.tf32.f32 "                 \
        "{%0,%1,%2,%3}, {%4,%5,%6,%7}, {%8,%9}, {%0,%1,%2,%3};\n"             \
        : "+f"((acc)[0]), "+f"((acc)[1]), "+f"((acc)[2]), "+f"((acc)[3])      \
        : "r"(a0), "r"(a1), "r"(a2), "r"(a3), "r"(b0), "r"(b1))

__device__ __forceinline__ void gemm_issue_tile(
    const float* __restrict__ A, const float* __restrict__ B,
    int N, int K, int bm, int bn, int k0,
    unsigned sA, unsigned sB, int t)
{
    #pragma unroll
    for (int i = 0; i < 4; i++) {
        int idx = i * 256 + t;
        int row = idx >> 3, kq = (idx & 7) << 2;
        const float* src = A + (size_t)(bm + row) * K + k0 + kq;
        unsigned dst = sA + (unsigned)(row * ASTR + kq) * 4u;
        asm volatile("cp.async.cg.shared.global [%0], [%1], 16;\n"
                     :: "r"(dst), "l"(src));
    }
    #pragma unroll
    for (int i = 0; i < 4; i++) {
        int idx = i * 256 + t;
        int row = idx >> 5, c = (idx & 31) << 2;
        int cg = bn + c;
        const float* src = B + (size_t)(k0 + row) * N + (cg < N ? cg : 0);
        int sz = (cg + 4 <= N) ? 16 : 0;
        unsigned dst = sB + (unsigned)(row * BSTR + c) * 4u;
        asm volatile("cp.async.cg.shared.global [%0], [%1], 16, %2;\n"
                     :: "r"(dst), "l"(src), "r"(sz));
    }
}

__global__ __launch_bounds__(256, 2) void tf32_gemm_kernel(
    const float* __restrict__ A, const float* __restrict__ B,
    float* __restrict__ C, int M, int N, int K)
{
    extern __shared__ __align__(16) float sm[];
    float* As[2] = { sm,            sm + STAGE_FLOATS };
    float* Bs[2] = { sm + STAGE_A,  sm + STAGE_FLOATS + STAGE_A };

    const int t    = threadIdx.x;
    const int bm   = blockIdx.y * GBM;
    const int bn   = blockIdx.x * GBN;
    const int wid  = t >> 5;
    const int lane = t & 31;
    const int gid  = lane >> 2;
    const int tig  = lane & 3;
    const int wm   = (wid & 1) * 64;
    const int wn   = (wid >> 1) * 32;

    unsigned sA_u[2], sB_u[2];
    sA_u[0] = smem_u32(As[0]); sA_u[1] = smem_u32(As[1]);
    sB_u[0] = smem_u32(Bs[0]); sB_u[1] = smem_u32(Bs[1]);

    float acc[4][4][4];
    #pragma unroll
    for (int mi = 0; mi < 4; mi++)
        #pragma unroll
        for (int ni = 0; ni < 4; ni++)
            #pragma unroll
            for (int e = 0; e < 4; e++) acc[mi][ni][e] = 0.0f;

    const int T = K / GBK;

    gemm_issue_tile(A, B, N, K, bm, bn, 0, sA_u[0], sB_u[0], t);
    asm volatile("cp.async.commit_group;\n");

    for (int tt = 0; tt < T; tt++) {
        if (tt + 1 < T)
            gemm_issue_tile(A, B, N, K, bm, bn, (tt + 1) * GBK,
                            sA_u[(tt + 1) & 1], sB_u[(tt + 1) & 1], t);
        asm volatile("cp.async.commit_group;\n");
        if (tt + 1 < T) asm volatile("cp.async.wait_group 1;\n");
        else            asm volatile("cp.async.wait_group 0;\n");
        __syncthreads();

        const float* as = As[tt & 1];
        const float* bs = Bs[tt & 1];

        #pragma unroll
        for (int k8 = 0; k8 < 4; k8++) {
            unsigned af[4][4];
            unsigned bf[4][2];
            #pragma unroll
            for (int mi = 0; mi < 4; mi++) {
                const float* p  = as + (wm + mi * 16 + gid) * ASTR + k8 * 8 + tig;
                const float* p2 = p + 8 * ASTR;
                af[mi][0] = __float_as_uint(p[0]);
                af[mi][1] = __float_as_uint(p2[0]);
                af[mi][2] = __float_as_uint(p[4]);
                af[mi][3] = __float_as_uint(p2[4]);
            }
            #pragma unroll
            for (int ni = 0; ni < 4; ni++) {
                const float* p = bs + (k8 * 8 + tig) * BSTR + wn + ni * 8 + gid;
                bf[ni][0] = __float_as_uint(p[0]);
                bf[ni][1] = __float_as_uint(p[4 * BSTR]);
            }
            #pragma unroll
            for (int mi = 0; mi < 4; mi++)
                #pragma unroll
                for (int ni = 0; ni < 4; ni++)
                    MMA_TF32(acc[mi][ni], af[mi][0], af[mi][1], af[mi][2],
                             af[mi][3], bf[ni][0], bf[ni][1]);
        }
        __syncthreads();
    }

    #pragma unroll
    for (int mi = 0; mi < 4; mi++) {
        int r = bm + wm + mi * 16 + gid;
        #pragma unroll
        for (int ni = 0; ni < 4; ni++) {
            int c = bn + wn + ni * 8 + tig * 2;
            if (c < N) {
                *(float2*)&C[(size_t)r * N + c] =
                    make_float2(acc[mi][ni][0], acc[mi][ni][1]);
                *(float2*)&C[(size_t)(r + 8) * N + c] =
                    make_float2(acc[mi][ni][2], acc[mi][ni][3]);
            }
        }
    }
}

// ---------------------------------------------------------------------------
// RoPE kernels (in place).
// ---------------------------------------------------------------------------
__global__ void rope_q_kernel(float* __restrict__ q)
{
    int idx = blockIdx.x * blockDim.x + threadIdx.x;
    if (idx >= MTOT * NH * 32) return;
    int j   = idx & 31;
    int h   = (idx >> 5) & (NH - 1);
    int row = idx >> 9;
    int s   = row & (SEQ - 1);

    double invd = exp(-(double)j * (9.210340371976184 / 32.0)); // ln(10000)/32
    float inv = (float)invd;
    float ang = (float)s * inv;
    float sn, cs;
    sincosf(ang, &sn, &cs);

    float* p = q + (size_t)row * QCOLS + h * DQK + DHD;
    float x1 = p[j], x2 = p[j + 32];
    p[j]      = x1 * cs - x2 * sn;
    p[j + 32] = x2 * cs + x1 * sn;
}

__global__ void rope_k_kernel(float* __restrict__ kr)
{
    int idx = blockIdx.x * blockDim.x + threadIdx.x;
    if (idx >= MTOT * 32) return;
    int j   = idx & 31;
    int row = idx >> 5;
    int s   = row & (SEQ - 1);

    double invd = exp(-(double)j * (9.210340371976184 / 32.0));
    float inv = (float)invd;
    float ang = (float)s * inv;
    float sn, cs;
    sincosf(ang, &sn, &cs);

    float* p = kr + (size_t)row * DRP;
    float x1 = p[j], x2 = p[j + 32];
    p[j]      = x1 * cs - x2 * sn;
    p[j + 32] = x2 * cs + x1 * sn;
}

// ---------------------------------------------------------------------------
// Flash attention (tensor core): BQ = BK = 64, d_qk = 192, d_v = 128, causal.
// 256 threads = 8 warps. QK^T: warp tile m16 x n32 (warps 4x2). PV: m16 x n64.
// Q/K/V are tf32-prerounded in gmem; P rounded in-register.
// Smem strides chosen for conflict-free fragment LDS:
//   AQS=196 (gid*4+tig), AVS=136 (tig*8+gid), ASS=68 (gid*4+tig).
// ---------------------------------------------------------------------------
#define AQS 196
#define AVS 136
#define ASS 68
#define ATTN_SMEM_FLOATS (64*AQS*2 + 64*AVS + 64*ASS + 3*64)
#define ATTN_SMEM_BYTES  (ATTN_SMEM_FLOATS * 4)

__global__ __launch_bounds__(256) void attn_kernel(
    const float* __restrict__ gq, const float* __restrict__ gkv,
    const float* __restrict__ gkr, float* __restrict__ gao)
{
    extern __shared__ float smf[];
    float* sQ  = smf;
    float* sK  = sQ + 64 * AQS;
    float* sV  = sK + 64 * AQS;
    float* sS  = sV + 64 * AVS;
    float* sMx = sS + 64 * ASS;
    float* sL  = sMx + 64;
    float* sC  = sL + 64;

    const int q0 = blockIdx.x * 64;
    const int h  = blockIdx.y;
    const int b  = blockIdx.z;
    const int t  = threadIdx.x;

    const int wid  = t >> 5;
    const int lane = t & 31;
    const int gid  = lane >> 2;     // 0..7
    const int tig  = lane & 3;      // 0..3
    const int wm   = (wid & 3) * 16;    // m offset (0..48)
    const int wnq  = (wid >> 2) * 32;   // QK n offset (0 or 32)
    const int wnv  = (wid >> 2) * 64;   // PV n offset (0 or 64)

    // Load Q tile
    for (int i = t; i < 64 * DQK; i += 256) {
        int r = i / DQK, d = i - r * DQK;
        sQ[r * AQS + d] = gq[(size_t)(b * SEQ + q0 + r) * QCOLS + h * DQK + d];
    }
    if (t < 64) { sMx[t] = -INFINITY; sL[t] = 0.0f; }

    float o[8][4];
    #pragma unroll
    for (int ni = 0; ni < 8; ni++)
        #pragma unroll
        for (int e = 0; e < 4; e++) o[ni][e] = 0.0f;

    const int ntiles = (q0 >> 6) + 1;
    const float scale = 0.07216878364870323f;  // 1/sqrt(192)

    for (int kt = 0; kt < ntiles; kt++) {
        const int k0 = kt << 6;
        __syncthreads();

        // Load K tile: [k_nope(128) | roped k_rope(64, head-broadcast)]
        for (int i = t; i < 64 * DQK; i += 256) {
            int r = i / DQK, d = i - r * DQK;
            size_t gr = (size_t)(b * SEQ + k0 + r);
            sK[r * AQS + d] = (d < DHD) ? gkv[gr * KVCOLS + h * 256 + d]
                                        : gkr[gr * DRP + (d - DHD)];
        }
        // Load V tile
        for (int i = t; i < 64 * DHD; i += 256) {
            int r = i >> 7, d = i & 127;
            sV[r * AVS + d] = gkv[(size_t)(b * SEQ + k0 + r) * KVCOLS + h * 256 + DHD + d];
        }
        __syncthreads();

        // ---- S = Q K^T via mma (K-dim 192 = 24 k8 steps) ----
        float sacc[4][4];
        #pragma unroll
        for (int ni = 0; ni < 4; ni++)
            #pragma unroll
            for (int e = 0; e < 4; e++) sacc[ni][e] = 0.0f;

        #pragma unroll 6
        for (int k8 = 0; k8 < DQK / 8; k8++) {
            const int kk = k8 * 8 + tig;
            const float* pa  = sQ + (wm + gid) * AQS + kk;
            const float* pa2 = pa + 8 * AQS;
            unsigned a0 = __float_as_uint(pa[0]);
            unsigned a1 = __float_as_uint(pa2[0]);
            unsigned a2 = __float_as_uint(pa[4]);
            unsigned a3 = __float_as_uint(pa2[4]);
            #pragma unroll
            for (int ni = 0; ni < 4; ni++) {
                const float* pb = sK + (wnq + ni * 8 + gid) * AQS + kk;
                unsigned b0 = __float_as_uint(pb[0]);
                unsigned b1 = __float_as_uint(pb[4]);
                MMA_TF32(sacc[ni], a0, a1, a2, a3, b0, b1);
            }
        }

        // Mask + scale + store score fragments to sS
        const bool diag = (k0 == q0);
        const int rg0 = wm + gid, rg1 = wm + gid + 8;
        #pragma unroll
        for (int ni = 0; ni < 4; ni++) {
            int cbase = wnq + ni * 8 + tig * 2;
            float v0 = sacc[ni][0] * scale;
            float v1 = sacc[ni][1] * scale;
            float v2 = sacc[ni][2] * scale;
            float v3 = sacc[ni][3] * scale;
            if (diag) {
                if (cbase     > rg0) v0 = -INFINITY;
                if (cbase + 1 > rg0) v1 = -INFINITY;
                if (cbase     > rg1) v2 = -INFINITY;
                if (cbase + 1 > rg1) v3 = -INFINITY;
            }
            *(float2*)&sS[rg0 * ASS + cbase] = make_float2(v0, v1);
            *(float2*)&sS[rg1 * ASS + cbase] = make_float2(v2, v3);
        }
        __syncthreads();

        // ---- Online softmax (one thread per row) ----
        if (t < 64) {
            float mo = sMx[t], mx = mo;
            #pragma unroll 8
            for (int j = 0; j < 64; j++) mx = fmaxf(mx, sS[t * ASS + j]);
            float c = __expf(mo - mx);       // 0 on first tile
            float l = sL[t] * c;
            #pragma unroll 8
            for (int j = 0; j < 64; j++) {
                float p = __expf(sS[t * ASS + j] - mx);
                sS[t * ASS + j] = p;
                l += p;
            }
            sMx[t] = mx; sL[t] = l; sC[t] = c;
        }
        __syncthreads();

        // ---- Rescale O, accumulate P @ V via mma (K-dim 64 = 8 k8) ----
        {
            float c0 = sC[rg0], c1 = sC[rg1];
            #pragma unroll
            for (int ni = 0; ni < 8; ni++) {
                o[ni][0] *= c0; o[ni][1] *= c0;
                o[ni][2] *= c1; o[ni][3] *= c1;
            }
        }

        #pragma unroll
        for (int k8 = 0; k8 < 8; k8++) {
            const int kk = k8 * 8 + tig;
            const float* pa  = sS + rg0 * ASS + kk;
            const float* pa2 = sS + rg1 * ASS + kk;
            unsigned a0 = tf32_rna_u(pa[0]);
            unsigned a1 = tf32_rna_u(pa2[0]);
            unsigned a2 = tf32_rna_u(pa[4]);
            unsigned a3 = tf32_rna_u(pa2[4]);
            #pragma unroll
            for (int ni = 0; ni < 8; ni++) {
                const float* pb = sV + kk * AVS + wnv + ni * 8 + gid;
                unsigned b0 = __float_as_uint(pb[0]);
                unsigned b1 = __float_as_uint(pb[4 * AVS]);
                MMA_TF32(o[ni], a0, a1, a2, a3, b0, b1);
            }
        }
    }

    // Epilogue: normalize and write
    {
        const int rg0 = wm + gid, rg1 = wm + gid + 8;
        float il0 = 1.0f / sL[rg0];
        float il1 = 1.0f / sL[rg1];
        size_t row0 = (size_t)(b * SEQ + q0 + rg0);
        size_t row1 = (size_t)(b * SEQ + q0 + rg1);
        #pragma unroll
        for (int ni = 0; ni < 8; ni++) {
            int c = h * DHD + wnv + ni * 8 + tig * 2;
            *(float2*)&gao[row0 * DIMM + c] =
                make_float2(o[ni][0] * il0, o[ni][1] * il0);
            *(float2*)&gao[row1 * DIMM + c] =
                make_float2(o[ni][2] * il1, o[ni][3] * il1);
        }
    }
}

// ---------------------------------------------------------------------------
// Launch
// ---------------------------------------------------------------------------
static void round_to_tf32(const float* src, float* dst, size_t n)
{
    int n4 = (int)(n / 4);
    int blocks = (n4 + 255) / 256;
    if (blocks > 8192) blocks = 8192;
    tf32_round_kernel<<<blocks, 256>>>(src, dst, n4);
}

extern "C" void kernel_launch(void* const* d_in, const int* in_sizes, int n_in,
                              void* d_out, int out_size)
{
    const float* x    = (const float*)d_in[0];
    const float* Wq   = (const float*)d_in[1];
    const float* Wdkv = (const float*)d_in[2];
    const float* Wkr  = (const float*)d_in[3];
    const float* Wukv = (const float*)d_in[4];
    const float* Wo   = (const float*)d_in[5];
    float* out = (float*)d_out;

    float *q, *ckv, *kr, *kv, *ao;
    float *xr, *wqr, *wdkvr, *wkrr, *wukvr, *wor;
    cudaGetSymbolAddress((void**)&q,     g_q);
    cudaGetSymbolAddress((void**)&ckv,   g_ckv);
    cudaGetSymbolAddress((void**)&kr,    g_kr);
    cudaGetSymbolAddress((void**)&kv,    g_kv);
    cudaGetSymbolAddress((void**)&ao,    g_ao);
    cudaGetSymbolAddress((void**)&xr,    g_xr);
    cudaGetSymbolAddress((void**)&wqr,   g_Wqr);
    cudaGetSymbolAddress((void**)&wdkvr, g_Wdkvr);
    cudaGetSymbolAddress((void**)&wkrr,  g_Wkrr);
    cudaGetSymbolAddress((void**)&wukvr, g_Wukvr);
    cudaGetSymbolAddress((void**)&wor,   g_Wor);

    cudaFuncSetAttribute(attn_kernel,
                         cudaFuncAttributeMaxDynamicSharedMemorySize,
                         ATTN_SMEM_BYTES);
    cudaFuncSetAttribute(tf32_gemm_kernel,
                         cudaFuncAttributeMaxDynamicSharedMemorySize,
                         GEMM_SMEM_BYTES);

    // Preround GEMM operands to tf32 (RNA) to avoid truncation bias in mma
    round_to_tf32(x,    xr,    (size_t)MTOT * DIMM);
    round_to_tf32(Wq,   wqr,   (size_t)DIMM * QCOLS);
    round_to_tf32(Wdkv, wdkvr, (size_t)DIMM * LATENT);
    round_to_tf32(Wkr,  wkrr,  (size_t)DIMM * DRP);
    round_to_tf32(Wukv, wukvr, (size_t)LATENT * KVCOLS);
    round_to_tf32(Wo,   wor,   (size_t)DIMM * DIMM);

    // Projections (tensor-core tf32)
    tf32_gemm_kernel<<<dim3(QCOLS / GBN, MTOT / GBM), 256, GEMM_SMEM_BYTES>>>(
        xr, wqr, q, MTOT, QCOLS, DIMM);
    tf32_gemm_kernel<<<dim3(LATENT / GBN, MTOT / GBM), 256, GEMM_SMEM_BYTES>>>(
        xr, wdkvr, ckv, MTOT, LATENT, DIMM);
    tf32_gemm_kernel<<<dim3(1, MTOT / GBM), 256, GEMM_SMEM_BYTES>>>(
        xr, wkrr, kr, MTOT, DRP, DIMM);

    // Round latent, then up-projection
    round_to_tf32(ckv, ckv, (size_t)MTOT * LATENT);
    tf32_gemm_kernel<<<dim3(KVCOLS / GBN, MTOT / GBM), 256, GEMM_SMEM_BYTES>>>(
        ckv, wukvr, kv, MTOT, KVCOLS, LATENT);

    // RoPE (in place)
    rope_q_kernel<<<(MTOT * NH * 32 + 255) / 256, 256>>>(q);
    rope_k_kernel<<<(MTOT * 32 + 255) / 256, 256>>>(kr);

    // Round attention operands in place (Q, K/V, k_rope)
    round_to_tf32(q,  q,  (size_t)MTOT * QCOLS);
    round_to_tf32(kv, kv, (size_t)MTOT * KVCOLS);
    round_to_tf32(kr, kr, (size_t)MTOT * DRP);

    // Attention (tensor-core tf32)
    attn_kernel<<<dim3(SEQ / 64, NH, BATCH), 256, ATTN_SMEM_BYTES>>>(q, kv, kr, ao);

    // Output projection
    round_to_tf32(ao, ao, (size_t)MTOT * DIMM);
    tf32_gemm_kernel<<<dim3(DIMM / GBN, MTOT / GBM), 256, GEMM_SMEM_BYTES>>>(
        ao, wor, out, MTOT, DIMM, DIMM);
}

// round 6
// speedup vs baseline: 2.8750x; 1.3684x over previous
#include <cuda_runtime.h>
#include <math.h>

// ---------------------------------------------------------------------------
// Problem constants
// ---------------------------------------------------------------------------
#define BATCH   2
#define SEQ     2048
#define MTOT    4096          // BATCH * SEQ
#define DIMM    2048
#define NH      16
#define DHD     128
#define DRP     64
#define DQK     192           // DHD + DRP
#define QCOLS   3072          // NH * DQK
#define KVCOLS  4096          // NH * 2 * DHD
#define LATENT  512

// ---------------------------------------------------------------------------
// Scratch (device globals; no runtime allocation allowed)
// ---------------------------------------------------------------------------
__device__ float g_q  [(size_t)MTOT * QCOLS];    // q (nope|rope), rope in place
__device__ float g_ckv[(size_t)MTOT * LATENT];
__device__ float g_kr [(size_t)MTOT * DRP];      // k_rope, rope in place
__device__ float g_kv [(size_t)MTOT * KVCOLS];   // per head: [k_nope(128) | v(128)]
__device__ float g_ao [(size_t)MTOT * DIMM];     // attention output (B,S,H*DH)

// tf32-prerounded operand copies (inputs only; intermediates rounded in-epilogue)
__device__ float g_xr   [(size_t)MTOT * DIMM];
__device__ float g_Wqr  [(size_t)DIMM * QCOLS];
__device__ float g_Wdkvr[(size_t)DIMM * LATENT];
__device__ float g_Wkrr [(size_t)DIMM * DRP];
__device__ float g_Wukvr[(size_t)LATENT * KVCOLS];
__device__ float g_Wor  [(size_t)DIMM * DIMM];

// ---------------------------------------------------------------------------
// tf32 round-to-nearest (cvt.rna) helpers
// ---------------------------------------------------------------------------
__device__ __forceinline__ float tf32_rna(float x)
{
    unsigned u;
    asm("cvt.rna.tf32.f32 %0, %1;" : "=r"(u) : "f"(x));
    return __uint_as_float(u);
}

__global__ void tf32_round_kernel(const float* __restrict__ in,
                                  float* __restrict__ out, int n4)
{
    int i = blockIdx.x * blockDim.x + threadIdx.x;
    int stride = gridDim.x * blockDim.x;
    for (; i < n4; i += stride) {
        float4 v = ((const float4*)in)[i];
        v.x = tf32_rna(v.x); v.y = tf32_rna(v.y);
        v.z = tf32_rna(v.z); v.w = tf32_rna(v.w);
        ((float4*)out)[i] = v;
    }
}

// ---------------------------------------------------------------------------
// tf32 tensor-core GEMM: C[M,N] = A[M,K] @ B[K,N], row-major fp32 (tf32-
// prerounded inputs). BM=BN=128, BK=32, 256 threads (8 warps, 64x32 warp
// tile), mma.sync.m16n8k8, cp.async double-buffered smem.
// ROUND: round outputs to tf32 in epilogue (for mma-consumed intermediates).
// ---------------------------------------------------------------------------
#define GBM 128
#define GBN 128
#define GBK 32
#define ASTR 36
#define BSTR 132
#define STAGE_A (GBM * ASTR)
#define STAGE_B (GBK * BSTR)
#define STAGE_FLOATS (STAGE_A + STAGE_B)
#define GEMM_SMEM_BYTES (2 * STAGE_FLOATS * 4)

__device__ __forceinline__ unsigned smem_u32(const void* p)
{
    unsigned a;
    asm("{ .reg .u64 t; cvta.to.shared.u64 t, %1; cvt.u32.u64 %0, t; }"
        : "=r"(a) : "l"(p));
    return a;
}

#define MMA_TF32(acc, a0, a1, a2, a3, b0, b1)                                 \
    asm volatile(                                                             \
        "mma.sync.aligned.m16n8k8.row.col.f32.tf32.tf32.f32 "                 \
        "{%0,%1,%2,%3}, {%4,%5,%6,%7}, {%8,%9}, {%0,%1,%2,%3};\n"             \
        : "+f"((acc)[0]), "+f"((acc)[1]), "+f"((acc)[2]), "+f"((acc)[3])      \
        : "r"(a0), "r"(a1), "r"(a2), "r"(a3), "r"(b0), "r"(b1))

__device__ __forceinline__ void gemm_issue_tile(
    const float* __restrict__ A, const float* __restrict__ B,
    int N, int K, int bm, int bn, int k0,
    unsigned sA, unsigned sB, int t)
{
    #pragma unroll
    for (int i = 0; i < 4; i++) {
        int idx = i * 256 + t;
        int row = idx >> 3, kq = (idx & 7) << 2;
        const float* src = A + (size_t)(bm + row) * K + k0 + kq;
        unsigned dst = sA + (unsigned)(row * ASTR + kq) * 4u;
        asm volatile("cp.async.cg.shared.global [%0], [%1], 16;\n"
                     :: "r"(dst), "l"(src));
    }
    #pragma unroll
    for (int i = 0; i < 4; i++) {
        int idx = i * 256 + t;
        int row = idx >> 5, c = (idx & 31) << 2;
        int cg = bn + c;
        const float* src = B + (size_t)(k0 + row) * N + (cg < N ? cg : 0);
        int sz = (cg + 4 <= N) ? 16 : 0;
        unsigned dst = sB + (unsigned)(row * BSTR + c) * 4u;
        asm volatile("cp.async.cg.shared.global [%0], [%1], 16, %2;\n"
                     :: "r"(dst), "l"(src), "r"(sz));
    }
}

template <bool ROUND>
__global__ __launch_bounds__(256, 2) void tf32_gemm_kernel(
    const float* __restrict__ A, const float* __restrict__ B,
    float* __restrict__ C, int M, int N, int K)
{
    extern __shared__ __align__(16) float sm[];
    float* As[2] = { sm,            sm + STAGE_FLOATS };
    float* Bs[2] = { sm + STAGE_A,  sm + STAGE_FLOATS + STAGE_A };

    const int t    = threadIdx.x;
    const int bm   = blockIdx.y * GBM;
    const int bn   = blockIdx.x * GBN;
    const int wid  = t >> 5;
    const int lane = t & 31;
    const int gid  = lane >> 2;
    const int tig  = lane & 3;
    const int wm   = (wid & 1) * 64;
    const int wn   = (wid >> 1) * 32;

    unsigned sA_u[2], sB_u[2];
    sA_u[0] = smem_u32(As[0]); sA_u[1] = smem_u32(As[1]);
    sB_u[0] = smem_u32(Bs[0]); sB_u[1] = smem_u32(Bs[1]);

    float acc[4][4][4];
    #pragma unroll
    for (int mi = 0; mi < 4; mi++)
        #pragma unroll
        for (int ni = 0; ni < 4; ni++)
            #pragma unroll
            for (int e = 0; e < 4; e++) acc[mi][ni][e] = 0.0f;

    const int T = K / GBK;

    gemm_issue_tile(A, B, N, K, bm, bn, 0, sA_u[0], sB_u[0], t);
    asm volatile("cp.async.commit_group;\n");

    for (int tt = 0; tt < T; tt++) {
        if (tt + 1 < T)
            gemm_issue_tile(A, B, N, K, bm, bn, (tt + 1) * GBK,
                            sA_u[(tt + 1) & 1], sB_u[(tt + 1) & 1], t);
        asm volatile("cp.async.commit_group;\n");
        if (tt + 1 < T) asm volatile("cp.async.wait_group 1;\n");
        else            asm volatile("cp.async.wait_group 0;\n");
        __syncthreads();

        const float* as = As[tt & 1];
        const float* bs = Bs[tt & 1];

        #pragma unroll
        for (int k8 = 0; k8 < 4; k8++) {
            unsigned af[4][4];
            unsigned bf[4][2];
            #pragma unroll
            for (int mi = 0; mi < 4; mi++) {
                const float* p  = as + (wm + mi * 16 + gid) * ASTR + k8 * 8 + tig;
                const float* p2 = p + 8 * ASTR;
                af[mi][0] = __float_as_uint(p[0]);
                af[mi][1] = __float_as_uint(p2[0]);
                af[mi][2] = __float_as_uint(p[4]);
                af[mi][3] = __float_as_uint(p2[4]);
            }
            #pragma unroll
            for (int ni = 0; ni < 4; ni++) {
                const float* p = bs + (k8 * 8 + tig) * BSTR + wn + ni * 8 + gid;
                bf[ni][0] = __float_as_uint(p[0]);
                bf[ni][1] = __float_as_uint(p[4 * BSTR]);
            }
            #pragma unroll
            for (int mi = 0; mi < 4; mi++)
                #pragma unroll
                for (int ni = 0; ni < 4; ni++)
                    MMA_TF32(acc[mi][ni], af[mi][0], af[mi][1], af[mi][2],
                             af[mi][3], bf[ni][0], bf[ni][1]);
        }
        __syncthreads();
    }

    #pragma unroll
    for (int mi = 0; mi < 4; mi++) {
        int r = bm + wm + mi * 16 + gid;
        #pragma unroll
        for (int ni = 0; ni < 4; ni++) {
            int c = bn + wn + ni * 8 + tig * 2;
            if (c < N) {
                float v0 = acc[mi][ni][0], v1 = acc[mi][ni][1];
                float v2 = acc[mi][ni][2], v3 = acc[mi][ni][3];
                if (ROUND) {
                    v0 = tf32_rna(v0); v1 = tf32_rna(v1);
                    v2 = tf32_rna(v2); v3 = tf32_rna(v3);
                }
                *(float2*)&C[(size_t)r * N + c]       = make_float2(v0, v1);
                *(float2*)&C[(size_t)(r + 8) * N + c] = make_float2(v2, v3);
            }
        }
    }
}

// ---------------------------------------------------------------------------
// RoPE kernels (in place). Outputs tf32-rounded (consumed by attention mma).
// ---------------------------------------------------------------------------
__global__ void rope_q_kernel(float* __restrict__ q)
{
    int idx = blockIdx.x * blockDim.x + threadIdx.x;
    if (idx >= MTOT * NH * 32) return;
    int j   = idx & 31;
    int h   = (idx >> 5) & (NH - 1);
    int row = idx >> 9;
    int s   = row & (SEQ - 1);

    double invd = exp(-(double)j * (9.210340371976184 / 32.0)); // ln(10000)/32
    float inv = (float)invd;
    float ang = (float)s * inv;
    float sn, cs;
    sincosf(ang, &sn, &cs);

    float* p = q + (size_t)row * QCOLS + h * DQK + DHD;
    float x1 = p[j], x2 = p[j + 32];
    p[j]      = tf32_rna(x1 * cs - x2 * sn);
    p[j + 32] = tf32_rna(x2 * cs + x1 * sn);
}

__global__ void rope_k_kernel(float* __restrict__ kr)
{
    int idx = blockIdx.x * blockDim.x + threadIdx.x;
    if (idx >= MTOT * 32) return;
    int j   = idx & 31;
    int row = idx >> 5;
    int s   = row & (SEQ - 1);

    double invd = exp(-(double)j * (9.210340371976184 / 32.0));
    float inv = (float)invd;
    float ang = (float)s * inv;
    float sn, cs;
    sincosf(ang, &sn, &cs);

    float* p = kr + (size_t)row * DRP;
    float x1 = p[j], x2 = p[j + 32];
    p[j]      = tf32_rna(x1 * cs - x2 * sn);
    p[j + 32] = tf32_rna(x2 * cs + x1 * sn);
}

// ---------------------------------------------------------------------------
// Flash attention (tensor core): BQ = BK = 64, d_qk = 192, d_v = 128, causal.
// 256 threads = 8 warps. QK^T: warp tile m16 x n32 (warps 4x2). PV: m16 x n64.
// Softmax fully distributed: shfl row-reductions over tig lanes + 128-float
// cross-warp-group staging (sPM/sPS). P written to sS once, tf32-rounded.
// ---------------------------------------------------------------------------
#define AQS 196
#define AVS 136
#define ASS 68
#define ATTN_SMEM_FLOATS (64*AQS*2 + 64*AVS + 64*ASS + 64 + 64 + 128 + 128)
#define ATTN_SMEM_BYTES  (ATTN_SMEM_FLOATS * 4)

__global__ __launch_bounds__(256) void attn_kernel(
    const float* __restrict__ gq, const float* __restrict__ gkv,
    const float* __restrict__ gkr, float* __restrict__ gao)
{
    extern __shared__ float smf[];
    float* sQ  = smf;
    float* sK  = sQ + 64 * AQS;
    float* sV  = sK + 64 * AQS;
    float* sS  = sV + 64 * AVS;     // P (post-exp, tf32)
    float* sMx = sS + 64 * ASS;     // running max per row
    float* sL  = sMx + 64;          // running sum per row
    float* sPM = sL + 64;           // partial max [group*64 + row]
    float* sPS = sPM + 128;         // partial sum [group*64 + row]

    const int q0 = blockIdx.x * 64;
    const int h  = blockIdx.y;
    const int b  = blockIdx.z;
    const int t  = threadIdx.x;

    const int wid  = t >> 5;
    const int lane = t & 31;
    const int gid  = lane >> 2;         // 0..7
    const int tig  = lane & 3;          // 0..3
    const int wm   = (wid & 3) * 16;    // m offset (0..48)
    const int grp  = wid >> 2;          // warp-column group (0 or 1)
    const int wnq  = grp * 32;          // QK n offset
    const int wnv  = grp * 64;          // PV n offset
    const int rg0  = wm + gid, rg1 = rg0 + 8;

    // Load Q tile (float4: 64 rows x 48 quads)
    for (int i = t; i < 64 * 48; i += 256) {
        int r = i / 48, c4 = i - r * 48;
        float4 v = *(const float4*)(gq + (size_t)(b * SEQ + q0 + r) * QCOLS
                                    + h * DQK + c4 * 4);
        *(float4*)&sQ[r * AQS + c4 * 4] = v;
    }
    if (t < 64) { sMx[t] = -INFINITY; sL[t] = 0.0f; }

    float o[8][4];
    #pragma unroll
    for (int ni = 0; ni < 8; ni++)
        #pragma unroll
        for (int e = 0; e < 4; e++) o[ni][e] = 0.0f;

    const int ntiles = (q0 >> 6) + 1;
    const float scale = 0.07216878364870323f;  // 1/sqrt(192)

    for (int kt = 0; kt < ntiles; kt++) {
        const int k0 = kt << 6;
        __syncthreads();  // prev PV done reading sS/sV; prev QK done with sK

        // K tile: cols [0,128) from kv (k_nope), [128,192) from kr (roped)
        for (int i = t; i < 64 * 48; i += 256) {
            int r = i / 48, c4 = i - r * 48;
            size_t gr = (size_t)(b * SEQ + k0 + r);
            float4 v = (c4 < 32)
                ? *(const float4*)(gkv + gr * KVCOLS + h * 256 + c4 * 4)
                : *(const float4*)(gkr + gr * DRP + (c4 - 32) * 4);
            *(float4*)&sK[r * AQS + c4 * 4] = v;
        }
        // V tile (64 x 32 quads)
        for (int i = t; i < 64 * 32; i += 256) {
            int r = i >> 5, c4 = i & 31;
            float4 v = *(const float4*)(gkv + (size_t)(b * SEQ + k0 + r) * KVCOLS
                                        + h * 256 + DHD + c4 * 4);
            *(float4*)&sV[r * AVS + c4 * 4] = v;
        }
        __syncthreads();

        // ---- S = Q K^T via mma (24 k8 steps) ----
        float sacc[4][4];
        #pragma unroll
        for (int ni = 0; ni < 4; ni++)
            #pragma unroll
            for (int e = 0; e < 4; e++) sacc[ni][e] = 0.0f;

        #pragma unroll 6
        for (int k8 = 0; k8 < DQK / 8; k8++) {
            const int kk = k8 * 8 + tig;
            const float* pa  = sQ + rg0 * AQS + kk;
            const float* pa2 = pa + 8 * AQS;
            unsigned a0 = __float_as_uint(pa[0]);
            unsigned a1 = __float_as_uint(pa2[0]);
            unsigned a2 = __float_as_uint(pa[4]);
            unsigned a3 = __float_as_uint(pa2[4]);
            #pragma unroll
            for (int ni = 0; ni < 4; ni++) {
                const float* pb = sK + (wnq + ni * 8 + gid) * AQS + kk;
                unsigned b0 = __float_as_uint(pb[0]);
                unsigned b1 = __float_as_uint(pb[4]);
                MMA_TF32(sacc[ni], a0, a1, a2, a3, b0, b1);
            }
        }

        // ---- Scale + mask in registers; per-row partial max ----
        const bool diag = (k0 == q0);
        float m0 = -INFINITY, m1 = -INFINITY;
        #pragma unroll
        for (int ni = 0; ni < 4; ni++) {
            int cbase = wnq + ni * 8 + tig * 2;
            float v0 = sacc[ni][0] * scale;
            float v1 = sacc[ni][1] * scale;
            float v2 = sacc[ni][2] * scale;
            float v3 = sacc[ni][3] * scale;
            if (diag) {
                if (cbase     > rg0) v0 = -INFINITY;
                if (cbase + 1 > rg0) v1 = -INFINITY;
                if (cbase     > rg1) v2 = -INFINITY;
                if (cbase + 1 > rg1) v3 = -INFINITY;
            }
            sacc[ni][0] = v0; sacc[ni][1] = v1;
            sacc[ni][2] = v2; sacc[ni][3] = v3;
            m0 = fmaxf(m0, fmaxf(v0, v1));
            m1 = fmaxf(m1, fmaxf(v2, v3));
        }
        // reduce over tig lanes (bits 0-1 of lane id)
        m0 = fmaxf(m0, __shfl_xor_sync(0xffffffffu, m0, 1));
        m0 = fmaxf(m0, __shfl_xor_sync(0xffffffffu, m0, 2));
        m1 = fmaxf(m1, __shfl_xor_sync(0xffffffffu, m1, 1));
        m1 = fmaxf(m1, __shfl_xor_sync(0xffffffffu, m1, 2));
        if (tig == 0) {
            sPM[grp * 64 + rg0] = m0;
            sPM[grp * 64 + rg1] = m1;
        }
        __syncthreads();

        // ---- exp in registers; write P to sS; partial sums ----
        float mo0 = sMx[rg0], mo1 = sMx[rg1];
        float mx0 = fmaxf(mo0, fmaxf(sPM[rg0], sPM[64 + rg0]));
        float mx1 = fmaxf(mo1, fmaxf(sPM[rg1], sPM[64 + rg1]));
        float c0 = __expf(mo0 - mx0);
        float c1 = __expf(mo1 - mx1);
        float l0 = 0.0f, l1 = 0.0f;
        #pragma unroll
        for (int ni = 0; ni < 4; ni++) {
            int cbase = wnq + ni * 8 + tig * 2;
            float p0 = __expf(sacc[ni][0] - mx0);
            float p1 = __expf(sacc[ni][1] - mx0);
            float p2 = __expf(sacc[ni][2] - mx1);
            float p3 = __expf(sacc[ni][3] - mx1);
            l0 += p0 + p1;
            l1 += p2 + p3;
            *(float2*)&sS[rg0 * ASS + cbase] =
                make_float2(tf32_rna(p0), tf32_rna(p1));
            *(float2*)&sS[rg1 * ASS + cbase] =
                make_float2(tf32_rna(p2), tf32_rna(p3));
        }
        l0 += __shfl_xor_sync(0xffffffffu, l0, 1);
        l0 += __shfl_xor_sync(0xffffffffu, l0, 2);
        l1 += __shfl_xor_sync(0xffffffffu, l1, 1);
        l1 += __shfl_xor_sync(0xffffffffu, l1, 2);
        if (tig == 0) {
            sPS[grp * 64 + rg0] = l0;
            sPS[grp * 64 + rg1] = l1;
        }
        __syncthreads();

        // ---- Update running stats (one thread per row) ----
        if (t < 64) {
            float mo = sMx[t];
            float mx = fmaxf(mo, fmaxf(sPM[t], sPM[64 + t]));
            float c  = __expf(mo - mx);
            sL[t] = sL[t] * c + sPS[t] + sPS[64 + t];
            sMx[t] = mx;
        }

        // ---- Rescale O (register c), accumulate P @ V via mma ----
        #pragma unroll
        for (int ni = 0; ni < 8; ni++) {
            o[ni][0] *= c0; o[ni][1] *= c0;
            o[ni][2] *= c1; o[ni][3] *= c1;
        }

        #pragma unroll
        for (int k8 = 0; k8 < 8; k8++) {
            const int kk = k8 * 8 + tig;
            const float* pa  = sS + rg0 * ASS + kk;
            const float* pa2 = sS + rg1 * ASS + kk;
            unsigned a0 = __float_as_uint(pa[0]);
            unsigned a1 = __float_as_uint(pa2[0]);
            unsigned a2 = __float_as_uint(pa[4]);
            unsigned a3 = __float_as_uint(pa2[4]);
            #pragma unroll
            for (int ni = 0; ni < 8; ni++) {
                const float* pb = sV + kk * AVS + wnv + ni * 8 + gid;
                unsigned b0 = __float_as_uint(pb[0]);
                unsigned b1 = __float_as_uint(pb[4 * AVS]);
                MMA_TF32(o[ni], a0, a1, a2, a3, b0, b1);
            }
        }
    }

    __syncthreads();  // final sL updates visible

    // Epilogue: normalize, round to tf32 (feeds Wo mma), write
    {
        float il0 = 1.0f / sL[rg0];
        float il1 = 1.0f / sL[rg1];
        size_t row0 = (size_t)(b * SEQ + q0 + rg0);
        size_t row1 = (size_t)(b * SEQ + q0 + rg1);
        #pragma unroll
        for (int ni = 0; ni < 8; ni++) {
            int c = h * DHD + wnv + ni * 8 + tig * 2;
            *(float2*)&gao[row0 * DIMM + c] =
                make_float2(tf32_rna(o[ni][0] * il0), tf32_rna(o[ni][1] * il0));
            *(float2*)&gao[row1 * DIMM + c] =
                make_float2(tf32_rna(o[ni][2] * il1), tf32_rna(o[ni][3] * il1));
        }
    }
}

// ---------------------------------------------------------------------------
// Launch
// ---------------------------------------------------------------------------
static void round_to_tf32(const float* src, float* dst, size_t n)
{
    int n4 = (int)(n / 4);
    int blocks = (n4 + 255) / 256;
    if (blocks > 8192) blocks = 8192;
    tf32_round_kernel<<<blocks, 256>>>(src, dst, n4);
}

extern "C" void kernel_launch(void* const* d_in, const int* in_sizes, int n_in,
                              void* d_out, int out_size)
{
    const float* x    = (const float*)d_in[0];
    const float* Wq   = (const float*)d_in[1];
    const float* Wdkv = (const float*)d_in[2];
    const float* Wkr  = (const float*)d_in[3];
    const float* Wukv = (const float*)d_in[4];
    const float* Wo   = (const float*)d_in[5];
    float* out = (float*)d_out;

    float *q, *ckv, *kr, *kv, *ao;
    float *xr, *wqr, *wdkvr, *wkrr, *wukvr, *wor;
    cudaGetSymbolAddress((void**)&q,     g_q);
    cudaGetSymbolAddress((void**)&ckv,   g_ckv);
    cudaGetSymbolAddress((void**)&kr,    g_kr);
    cudaGetSymbolAddress((void**)&kv,    g_kv);
    cudaGetSymbolAddress((void**)&ao,    g_ao);
    cudaGetSymbolAddress((void**)&xr,    g_xr);
    cudaGetSymbolAddress((void**)&wqr,   g_Wqr);
    cudaGetSymbolAddress((void**)&wdkvr, g_Wdkvr);
    cudaGetSymbolAddress((void**)&wkrr,  g_Wkrr);
    cudaGetSymbolAddress((void**)&wukvr, g_Wukvr);
    cudaGetSymbolAddress((void**)&wor,   g_Wor);

    cudaFuncSetAttribute(attn_kernel,
                         cudaFuncAttributeMaxDynamicSharedMemorySize,
                         ATTN_SMEM_BYTES);
    cudaFuncSetAttribute(tf32_gemm_kernel<true>,
                         cudaFuncAttributeMaxDynamicSharedMemorySize,
                         GEMM_SMEM_BYTES);
    cudaFuncSetAttribute(tf32_gemm_kernel<false>,
                         cudaFuncAttributeMaxDynamicSharedMemorySize,
                         GEMM_SMEM_BYTES);

    // Preround GEMM inputs to tf32 (RNA); intermediates rounded in epilogues
    round_to_tf32(x,    xr,    (size_t)MTOT * DIMM);
    round_to_tf32(Wq,   wqr,   (size_t)DIMM * QCOLS);
    round_to_tf32(Wdkv, wdkvr, (size_t)DIMM * LATENT);
    round_to_tf32(Wkr,  wkrr,  (size_t)DIMM * DRP);
    round_to_tf32(Wukv, wukvr, (size_t)LATENT * KVCOLS);
    round_to_tf32(Wo,   wor,   (size_t)DIMM * DIMM);

    // Projections (tensor-core tf32; outputs rounded for downstream mma)
    tf32_gemm_kernel<true><<<dim3(QCOLS / GBN, MTOT / GBM), 256, GEMM_SMEM_BYTES>>>(
        xr, wqr, q, MTOT, QCOLS, DIMM);
    tf32_gemm_kernel<true><<<dim3(LATENT / GBN, MTOT / GBM), 256, GEMM_SMEM_BYTES>>>(
        xr, wdkvr, ckv, MTOT, LATENT, DIMM);
    tf32_gemm_kernel<true><<<dim3(1, MTOT / GBM), 256, GEMM_SMEM_BYTES>>>(
        xr, wkrr, kr, MTOT, DRP, DIMM);
    tf32_gemm_kernel<true><<<dim3(KVCOLS / GBN, MTOT / GBM), 256, GEMM_SMEM_BYTES>>>(
        ckv, wukvr, kv, MTOT, KVCOLS, LATENT);

    // RoPE (in place, outputs tf32-rounded)
    rope_q_kernel<<<(MTOT * NH * 32 + 255) / 256, 256>>>(q);
    rope_k_kernel<<<(MTOT * 32 + 255) / 256, 256>>>(kr);

    // Attention (tensor-core tf32; output tf32-rounded)
    attn_kernel<<<dim3(SEQ / 64, NH, BATCH), 256, ATTN_SMEM_BYTES>>>(q, kv, kr, ao);

    // Output projection (fp32 output, no rounding)
    tf32_gemm_kernel<false><<<dim3(DIMM / GBN, MTOT / GBM), 256, GEMM_SMEM_BYTES>>>(
        ao, wor, out, MTOT, DIMM, DIMM);
}

// round 7
// speedup vs baseline: 3.4185x; 1.1890x over previous
#include <cuda_runtime.h>
#include <math.h>

// ---------------------------------------------------------------------------
// Problem constants
// ---------------------------------------------------------------------------
#define BATCH   2
#define SEQ     2048
#define MTOT    4096          // BATCH * SEQ
#define DIMM    2048
#define NH      16
#define DHD     128
#define DRP     64
#define DQK     192           // DHD + DRP
#define QCOLS   3072          // NH * DQK
#define KVCOLS  4096          // NH * 2 * DHD
#define LATENT  512

// ---------------------------------------------------------------------------
// Scratch (device globals; no runtime allocation allowed)
// ---------------------------------------------------------------------------
__device__ float g_q  [(size_t)MTOT * QCOLS];    // q (nope|rope), rope in place
__device__ float g_ckv[(size_t)MTOT * LATENT];
__device__ float g_kr [(size_t)MTOT * DRP];      // k_rope, rope in place
__device__ float g_kv [(size_t)MTOT * KVCOLS];   // per head: [k_nope(128) | v(128)]
__device__ float g_ao [(size_t)MTOT * DIMM];     // attention output (B,S,H*DH)

// tf32-prerounded operand copies (inputs only; intermediates rounded in-epilogue)
__device__ float g_xr   [(size_t)MTOT * DIMM];
__device__ float g_Wqr  [(size_t)DIMM * QCOLS];
__device__ float g_Wdkvr[(size_t)DIMM * LATENT];
__device__ float g_Wkrr [(size_t)DIMM * DRP];
__device__ float g_Wukvr[(size_t)LATENT * KVCOLS];
__device__ float g_Wor  [(size_t)DIMM * DIMM];

// ---------------------------------------------------------------------------
// tf32 round-to-nearest (cvt.rna) helpers
// ---------------------------------------------------------------------------
__device__ __forceinline__ float tf32_rna(float x)
{
    unsigned u;
    asm("cvt.rna.tf32.f32 %0, %1;" : "=r"(u) : "f"(x));
    return __uint_as_float(u);
}

__global__ void tf32_round_kernel(const float* __restrict__ in,
                                  float* __restrict__ out, int n4)
{
    int i = blockIdx.x * blockDim.x + threadIdx.x;
    int stride = gridDim.x * blockDim.x;
    for (; i < n4; i += stride) {
        float4 v = ((const float4*)in)[i];
        v.x = tf32_rna(v.x); v.y = tf32_rna(v.y);
        v.z = tf32_rna(v.z); v.w = tf32_rna(v.w);
        ((float4*)out)[i] = v;
    }
}

// ---------------------------------------------------------------------------
// tf32 tensor-core GEMM: C[M,N] = A[M,K] @ B[K,N], row-major fp32 (tf32-
// prerounded inputs). BM=BN=128, BK=32, 256 threads (8 warps, 64x32 warp
// tile), mma.sync.m16n8k8, cp.async double-buffered smem.
// ROUND: round outputs to tf32 in epilogue (for mma-consumed intermediates).
// ---------------------------------------------------------------------------
#define GBM 128
#define GBN 128
#define GBK 32
#define ASTR 36
#define BSTR 132
#define STAGE_A (GBM * ASTR)
#define STAGE_B (GBK * BSTR)
#define STAGE_FLOATS (STAGE_A + STAGE_B)
#define GEMM_SMEM_BYTES (2 * STAGE_FLOATS * 4)

__device__ __forceinline__ unsigned smem_u32(const void* p)
{
    unsigned a;
    asm("{ .reg .u64 t; cvta.to.shared.u64 t, %1; cvt.u32.u64 %0, t; }"
        : "=r"(a) : "l"(p));
    return a;
}

#define MMA_TF32(acc, a0, a1, a2, a3, b0, b1)                                 \
    asm volatile(                                                             \
        "mma.sync.aligned.m16n8k8.row.col.f32.tf32.tf32.f32 "                 \
        "{%0,%1,%2,%3}, {%4,%5,%6,%7}, {%8,%9}, {%0,%1,%2,%3};\n"             \
        : "+f"((acc)[0]), "+f"((acc)[1]), "+f"((acc)[2]), "+f"((acc)[3])      \
        : "r"(a0), "r"(a1), "r"(a2), "r"(a3), "r"(b0), "r"(b1))

__device__ __forceinline__ void gemm_issue_tile(
    const float* __restrict__ A, const float* __restrict__ B,
    int N, int K, int bm, int bn, int k0,
    unsigned sA, unsigned sB, int t)
{
    #pragma unroll
    for (int i = 0; i < 4; i++) {
        int idx = i * 256 + t;
        int row = idx >> 3, kq = (idx & 7) << 2;
        const float* src = A + (size_t)(bm + row) * K + k0 + kq;
        unsigned dst = sA + (unsigned)(row * ASTR + kq) * 4u;
        asm volatile("cp.async.cg.shared.global [%0], [%1], 16;\n"
                     :: "r"(dst), "l"(src));
    }
    #pragma unroll
    for (int i = 0; i < 4; i++) {
        int idx = i * 256 + t;
        int row = idx >> 5, c = (idx & 31) << 2;
        int cg = bn + c;
        const float* src = B + (size_t)(k0 + row) * N + (cg < N ? cg : 0);
        int sz = (cg + 4 <= N) ? 16 : 0;
        unsigned dst = sB + (unsigned)(row * BSTR + c) * 4u;
        asm volatile("cp.async.cg.shared.global [%0], [%1], 16, %2;\n"
                     :: "r"(dst), "l"(src), "r"(sz));
    }
}

template <bool ROUND>
__global__ __launch_bounds__(256, 2) void tf32_gemm_kernel(
    const float* __restrict__ A, const float* __restrict__ B,
    float* __restrict__ C, int M, int N, int K)
{
    extern __shared__ __align__(16) float sm[];
    float* As[2] = { sm,            sm + STAGE_FLOATS };
    float* Bs[2] = { sm + STAGE_A,  sm + STAGE_FLOATS + STAGE_A };

    const int t    = threadIdx.x;
    const int bm   = blockIdx.y * GBM;
    const int bn   = blockIdx.x * GBN;
    const int wid  = t >> 5;
    const int lane = t & 31;
    const int gid  = lane >> 2;
    const int tig  = lane & 3;
    const int wm   = (wid & 1) * 64;
    const int wn   = (wid >> 1) * 32;

    unsigned sA_u[2], sB_u[2];
    sA_u[0] = smem_u32(As[0]); sA_u[1] = smem_u32(As[1]);
    sB_u[0] = smem_u32(Bs[0]); sB_u[1] = smem_u32(Bs[1]);

    float acc[4][4][4];
    #pragma unroll
    for (int mi = 0; mi < 4; mi++)
        #pragma unroll
        for (int ni = 0; ni < 4; ni++)
            #pragma unroll
            for (int e = 0; e < 4; e++) acc[mi][ni][e] = 0.0f;

    const int T = K / GBK;

    gemm_issue_tile(A, B, N, K, bm, bn, 0, sA_u[0], sB_u[0], t);
    asm volatile("cp.async.commit_group;\n");

    for (int tt = 0; tt < T; tt++) {
        if (tt + 1 < T)
            gemm_issue_tile(A, B, N, K, bm, bn, (tt + 1) * GBK,
                            sA_u[(tt + 1) & 1], sB_u[(tt + 1) & 1], t);
        asm volatile("cp.async.commit_group;\n");
        if (tt + 1 < T) asm volatile("cp.async.wait_group 1;\n");
        else            asm volatile("cp.async.wait_group 0;\n");
        __syncthreads();

        const float* as = As[tt & 1];
        const float* bs = Bs[tt & 1];

        #pragma unroll
        for (int k8 = 0; k8 < 4; k8++) {
            unsigned af[4][4];
            unsigned bf[4][2];
            #pragma unroll
            for (int mi = 0; mi < 4; mi++) {
                const float* p  = as + (wm + mi * 16 + gid) * ASTR + k8 * 8 + tig;
                const float* p2 = p + 8 * ASTR;
                af[mi][0] = __float_as_uint(p[0]);
                af[mi][1] = __float_as_uint(p2[0]);
                af[mi][2] = __float_as_uint(p[4]);
                af[mi][3] = __float_as_uint(p2[4]);
            }
            #pragma unroll
            for (int ni = 0; ni < 4; ni++) {
                const float* p = bs + (k8 * 8 + tig) * BSTR + wn + ni * 8 + gid;
                bf[ni][0] = __float_as_uint(p[0]);
                bf[ni][1] = __float_as_uint(p[4 * BSTR]);
            }
            #pragma unroll
            for (int mi = 0; mi < 4; mi++)
                #pragma unroll
                for (int ni = 0; ni < 4; ni++)
                    MMA_TF32(acc[mi][ni], af[mi][0], af[mi][1], af[mi][2],
                             af[mi][3], bf[ni][0], bf[ni][1]);
        }
        __syncthreads();
    }

    #pragma unroll
    for (int mi = 0; mi < 4; mi++) {
        int r = bm + wm + mi * 16 + gid;
        #pragma unroll
        for (int ni = 0; ni < 4; ni++) {
            int c = bn + wn + ni * 8 + tig * 2;
            if (c < N) {
                float v0 = acc[mi][ni][0], v1 = acc[mi][ni][1];
                float v2 = acc[mi][ni][2], v3 = acc[mi][ni][3];
                if (ROUND) {
                    v0 = tf32_rna(v0); v1 = tf32_rna(v1);
                    v2 = tf32_rna(v2); v3 = tf32_rna(v3);
                }
                *(float2*)&C[(size_t)r * N + c]       = make_float2(v0, v1);
                *(float2*)&C[(size_t)(r + 8) * N + c] = make_float2(v2, v3);
            }
        }
    }
}

// ---------------------------------------------------------------------------
// RoPE kernels (in place). Outputs tf32-rounded (consumed by attention mma).
// ---------------------------------------------------------------------------
__global__ void rope_q_kernel(float* __restrict__ q)
{
    int idx = blockIdx.x * blockDim.x + threadIdx.x;
    if (idx >= MTOT * NH * 32) return;
    int j   = idx & 31;
    int h   = (idx >> 5) & (NH - 1);
    int row = idx >> 9;
    int s   = row & (SEQ - 1);

    double invd = exp(-(double)j * (9.210340371976184 / 32.0)); // ln(10000)/32
    float inv = (float)invd;
    float ang = (float)s * inv;
    float sn, cs;
    sincosf(ang, &sn, &cs);

    float* p = q + (size_t)row * QCOLS + h * DQK + DHD;
    float x1 = p[j], x2 = p[j + 32];
    p[j]      = tf32_rna(x1 * cs - x2 * sn);
    p[j + 32] = tf32_rna(x2 * cs + x1 * sn);
}

__global__ void rope_k_kernel(float* __restrict__ kr)
{
    int idx = blockIdx.x * blockDim.x + threadIdx.x;
    if (idx >= MTOT * 32) return;
    int j   = idx & 31;
    int row = idx >> 5;
    int s   = row & (SEQ - 1);

    double invd = exp(-(double)j * (9.210340371976184 / 32.0));
    float inv = (float)invd;
    float ang = (float)s * inv;
    float sn, cs;
    sincosf(ang, &sn, &cs);

    float* p = kr + (size_t)row * DRP;
    float x1 = p[j], x2 = p[j + 32];
    p[j]      = tf32_rna(x1 * cs - x2 * sn);
    p[j + 32] = tf32_rna(x2 * cs + x1 * sn);
}

// ---------------------------------------------------------------------------
// Flash attention (tensor core): BQ = 64, BK = 32, d_qk = 192, d_v = 128,
// causal. 256 threads = 8 warps. cp.async double-buffered K/V tiles.
// QK^T: warp tile m16 x n16 (warps 4x2). PV: m16 x n64.
// Smem: sQ 64x196, sK 2x32x196, sV 2x32x136, sS 64x36 (~146 KB).
// ---------------------------------------------------------------------------
#define BKT 32
#define AQS 196
#define AVS 136
#define ASS 36
#define KSTG (BKT * AQS)     // 6272 floats per K stage
#define VSTG (BKT * AVS)     // 4352 floats per V stage
#define ATTN_SMEM_FLOATS (64*AQS + 2*KSTG + 2*VSTG + 64*ASS + 64 + 64 + 128 + 128)
#define ATTN_SMEM_BYTES  (ATTN_SMEM_FLOATS * 4)

__global__ __launch_bounds__(256) void attn_kernel(
    const float* __restrict__ gq, const float* __restrict__ gkv,
    const float* __restrict__ gkr, float* __restrict__ gao)
{
    extern __shared__ __align__(16) float smf[];
    float* sQ  = smf;
    float* sK0 = sQ + 64 * AQS;
    float* sV0 = sK0 + 2 * KSTG;
    float* sS  = sV0 + 2 * VSTG;    // P (post-exp, tf32)
    float* sMx = sS + 64 * ASS;     // running max per row
    float* sL  = sMx + 64;          // running sum per row
    float* sPM = sL + 64;           // partial max [group*64 + row]
    float* sPS = sPM + 128;         // partial sum [group*64 + row]

    const int q0 = blockIdx.x * 64;
    const int h  = blockIdx.y;
    const int b  = blockIdx.z;
    const int t  = threadIdx.x;

    const int wid  = t >> 5;
    const int lane = t & 31;
    const int gid  = lane >> 2;         // 0..7
    const int tig  = lane & 3;          // 0..3
    const int wm   = (wid & 3) * 16;    // m offset (0..48)
    const int grp  = wid >> 2;          // warp-column group (0 or 1)
    const int wnq  = grp * 16;          // QK n offset (n16 per group)
    const int wnv  = grp * 64;          // PV n offset
    const int rg0  = wm + gid, rg1 = rg0 + 8;

    const unsigned sKu = smem_u32(sK0);
    const unsigned sVu = smem_u32(sV0);

    // Load Q tile (float4: 64 rows x 48 quads)
    for (int i = t; i < 64 * 48; i += 256) {
        int r = i / 48, c4 = i - r * 48;
        float4 v = *(const float4*)(gq + (size_t)(b * SEQ + q0 + r) * QCOLS
                                    + h * DQK + c4 * 4);
        *(float4*)&sQ[r * AQS + c4 * 4] = v;
    }
    if (t < 64) { sMx[t] = -INFINITY; sL[t] = 0.0f; }

    float o[8][4];
    #pragma unroll
    for (int ni = 0; ni < 8; ni++)
        #pragma unroll
        for (int e = 0; e < 4; e++) o[ni][e] = 0.0f;

    const int ntiles = (q0 >> 5) + 2;           // k up to q0 + 63
    const float scale = 0.07216878364870323f;   // 1/sqrt(192)

    // cp.async issue of K/V stage for tile kt
    auto issue_kv = [&](int kt) {
        const int k0 = kt << 5;
        const unsigned kb = sKu + (unsigned)((kt & 1) * KSTG) * 4u;
        const unsigned vb = sVu + (unsigned)((kt & 1) * VSTG) * 4u;
        #pragma unroll
        for (int i = 0; i < 6; i++) {           // 32 rows x 48 quads
            int idx = i * 256 + t;
            int r = idx / 48, c4 = idx - r * 48;
            size_t gr = (size_t)(b * SEQ + k0 + r);
            const float* src = (c4 < 32)
                ? gkv + gr * KVCOLS + h * 256 + c4 * 4
                : gkr + gr * DRP + (c4 - 32) * 4;
            asm volatile("cp.async.cg.shared.global [%0], [%1], 16;\n"
                         :: "r"(kb + (unsigned)(r * AQS + c4 * 4) * 4u), "l"(src));
        }
        #pragma unroll
        for (int i = 0; i < 4; i++) {           // 32 rows x 32 quads
            int idx = i * 256 + t;
            int r = idx >> 5, c4 = idx & 31;
            const float* src = gkv + (size_t)(b * SEQ + k0 + r) * KVCOLS
                               + h * 256 + DHD + c4 * 4;
            asm volatile("cp.async.cg.shared.global [%0], [%1], 16;\n"
                         :: "r"(vb + (unsigned)(r * AVS + c4 * 4) * 4u), "l"(src));
        }
        asm volatile("cp.async.commit_group;\n");
    };

    issue_kv(0);

    for (int kt = 0; kt < ntiles; kt++) {
        const int k0 = kt << 5;
        if (kt + 1 < ntiles) {
            issue_kv(kt + 1);
            asm volatile("cp.async.wait_group 1;\n");
        } else {
            asm volatile("cp.async.wait_group 0;\n");
        }
        __syncthreads();   // stage kt ready; prev compute done (buffer reuse)

        const float* sK = sK0 + (kt & 1) * KSTG;
        const float* sV = sV0 + (kt & 1) * VSTG;

        // ---- S = Q K^T via mma (24 k8 steps, 2 n8 tiles/warp) ----
        float sacc[2][4];
        #pragma unroll
        for (int ni = 0; ni < 2; ni++)
            #pragma unroll
            for (int e = 0; e < 4; e++) sacc[ni][e] = 0.0f;

        #pragma unroll 6
        for (int k8 = 0; k8 < DQK / 8; k8++) {
            const int kk = k8 * 8 + tig;
            const float* pa  = sQ + rg0 * AQS + kk;
            const float* pa2 = pa + 8 * AQS;
            unsigned a0 = __float_as_uint(pa[0]);
            unsigned a1 = __float_as_uint(pa2[0]);
            unsigned a2 = __float_as_uint(pa[4]);
            unsigned a3 = __float_as_uint(pa2[4]);
            #pragma unroll
            for (int ni = 0; ni < 2; ni++) {
                const float* pb = sK + (wnq + ni * 8 + gid) * AQS + kk;
                unsigned b0 = __float_as_uint(pb[0]);
                unsigned b1 = __float_as_uint(pb[4]);
                MMA_TF32(sacc[ni], a0, a1, a2, a3, b0, b1);
            }
        }

        // ---- Scale + mask in registers; per-row partial max ----
        const int koff = k0 - q0;               // mask needed iff koff >= 0
        const bool needmask = (koff >= 0);
        float m0 = -INFINITY, m1 = -INFINITY;
        #pragma unroll
        for (int ni = 0; ni < 2; ni++) {
            int cbase = wnq + ni * 8 + tig * 2;
            float v0 = sacc[ni][0] * scale;
            float v1 = sacc[ni][1] * scale;
            float v2 = sacc[ni][2] * scale;
            float v3 = sacc[ni][3] * scale;
            if (needmask) {
                if (koff + cbase     > rg0) v0 = -INFINITY;
                if (koff + cbase + 1 > rg0) v1 = -INFINITY;
                if (koff + cbase     > rg1) v2 = -INFINITY;
                if (koff + cbase + 1 > rg1) v3 = -INFINITY;
            }
            sacc[ni][0] = v0; sacc[ni][1] = v1;
            sacc[ni][2] = v2; sacc[ni][3] = v3;
            m0 = fmaxf(m0, fmaxf(v0, v1));
            m1 = fmaxf(m1, fmaxf(v2, v3));
        }
        m0 = fmaxf(m0, __shfl_xor_sync(0xffffffffu, m0, 1));
        m0 = fmaxf(m0, __shfl_xor_sync(0xffffffffu, m0, 2));
        m1 = fmaxf(m1, __shfl_xor_sync(0xffffffffu, m1, 1));
        m1 = fmaxf(m1, __shfl_xor_sync(0xffffffffu, m1, 2));
        if (tig == 0) {
            sPM[grp * 64 + rg0] = m0;
            sPM[grp * 64 + rg1] = m1;
        }
        __syncthreads();

        // ---- exp in registers; write P to sS; partial sums ----
        float mo0 = sMx[rg0], mo1 = sMx[rg1];
        float mx0 = fmaxf(mo0, fmaxf(sPM[rg0], sPM[64 + rg0]));
        float mx1 = fmaxf(mo1, fmaxf(sPM[rg1], sPM[64 + rg1]));
        float c0 = __expf(mo0 - mx0);
        float c1 = __expf(mo1 - mx1);
        float l0 = 0.0f, l1 = 0.0f;
        #pragma unroll
        for (int ni = 0; ni < 2; ni++) {
            int cbase = wnq + ni * 8 + tig * 2;
            float p0 = __expf(sacc[ni][0] - mx0);
            float p1 = __expf(sacc[ni][1] - mx0);
            float p2 = __expf(sacc[ni][2] - mx1);
            float p3 = __expf(sacc[ni][3] - mx1);
            l0 += p0 + p1;
            l1 += p2 + p3;
            *(float2*)&sS[rg0 * ASS + cbase] =
                make_float2(tf32_rna(p0), tf32_rna(p1));
            *(float2*)&sS[rg1 * ASS + cbase] =
                make_float2(tf32_rna(p2), tf32_rna(p3));
        }
        l0 += __shfl_xor_sync(0xffffffffu, l0, 1);
        l0 += __shfl_xor_sync(0xffffffffu, l0, 2);
        l1 += __shfl_xor_sync(0xffffffffu, l1, 1);
        l1 += __shfl_xor_sync(0xffffffffu, l1, 2);
        if (tig == 0) {
            sPS[grp * 64 + rg0] = l0;
            sPS[grp * 64 + rg1] = l1;
        }
        __syncthreads();

        // ---- Update running stats (one thread per row) ----
        if (t < 64) {
            float mo = sMx[t];
            float mx = fmaxf(mo, fmaxf(sPM[t], sPM[64 + t]));
            float c  = __expf(mo - mx);
            sL[t] = sL[t] * c + sPS[t] + sPS[64 + t];
            sMx[t] = mx;
        }

        // ---- Rescale O, accumulate P @ V via mma (4 k8 steps) ----
        #pragma unroll
        for (int ni = 0; ni < 8; ni++) {
            o[ni][0] *= c0; o[ni][1] *= c0;
            o[ni][2] *= c1; o[ni][3] *= c1;
        }

        #pragma unroll
        for (int k8 = 0; k8 < 4; k8++) {
            const int kk = k8 * 8 + tig;
            const float* pa  = sS + rg0 * ASS + kk;
            const float* pa2 = sS + rg1 * ASS + kk;
            unsigned a0 = __float_as_uint(pa[0]);
            unsigned a1 = __float_as_uint(pa2[0]);
            unsigned a2 = __float_as_uint(pa[4]);
            unsigned a3 = __float_as_uint(pa2[4]);
            #pragma unroll
            for (int ni = 0; ni < 8; ni++) {
                const float* pb = sV + kk * AVS + wnv + ni * 8 + gid;
                unsigned b0 = __float_as_uint(pb[0]);
                unsigned b1 = __float_as_uint(pb[4 * AVS]);
                MMA_TF32(o[ni], a0, a1, a2, a3, b0, b1);
            }
        }
        __syncthreads();   // compute on this buffer done before next prefetch
    }

    // Epilogue: normalize, round to tf32 (feeds Wo mma), write
    {
        float il0 = 1.0f / sL[rg0];
        float il1 = 1.0f / sL[rg1];
        size_t row0 = (size_t)(b * SEQ + q0 + rg0);
        size_t row1 = (size_t)(b * SEQ + q0 + rg1);
        #pragma unroll
        for (int ni = 0; ni < 8; ni++) {
            int c = h * DHD + wnv + ni * 8 + tig * 2;
            *(float2*)&gao[row0 * DIMM + c] =
                make_float2(tf32_rna(o[ni][0] * il0), tf32_rna(o[ni][1] * il0));
            *(float2*)&gao[row1 * DIMM + c] =
                make_float2(tf32_rna(o[ni][2] * il1), tf32_rna(o[ni][3] * il1));
        }
    }
}

// ---------------------------------------------------------------------------
// Launch
// ---------------------------------------------------------------------------
static void round_to_tf32(const float* src, float* dst, size_t n)
{
    int n4 = (int)(n / 4);
    int blocks = (n4 + 255) / 256;
    if (blocks > 8192) blocks = 8192;
    tf32_round_kernel<<<blocks, 256>>>(src, dst, n4);
}

extern "C" void kernel_launch(void* const* d_in, const int* in_sizes, int n_in,
                              void* d_out, int out_size)
{
    const float* x    = (const float*)d_in[0];
    const float* Wq   = (const float*)d_in[1];
    const float* Wdkv = (const float*)d_in[2];
    const float* Wkr  = (const float*)d_in[3];
    const float* Wukv = (const float*)d_in[4];
    const float* Wo   = (const float*)d_in[5];
    float* out = (float*)d_out;

    float *q, *ckv, *kr, *kv, *ao;
    float *xr, *wqr, *wdkvr, *wkrr, *wukvr, *wor;
    cudaGetSymbolAddress((void**)&q,     g_q);
    cudaGetSymbolAddress((void**)&ckv,   g_ckv);
    cudaGetSymbolAddress((void**)&kr,    g_kr);
    cudaGetSymbolAddress((void**)&kv,    g_kv);
    cudaGetSymbolAddress((void**)&ao,    g_ao);
    cudaGetSymbolAddress((void**)&xr,    g_xr);
    cudaGetSymbolAddress((void**)&wqr,   g_Wqr);
    cudaGetSymbolAddress((void**)&wdkvr, g_Wdkvr);
    cudaGetSymbolAddress((void**)&wkrr,  g_Wkrr);
    cudaGetSymbolAddress((void**)&wukvr, g_Wukvr);
    cudaGetSymbolAddress((void**)&wor,   g_Wor);

    cudaFuncSetAttribute(attn_kernel,
                         cudaFuncAttributeMaxDynamicSharedMemorySize,
                         ATTN_SMEM_BYTES);
    cudaFuncSetAttribute(tf32_gemm_kernel<true>,
                         cudaFuncAttributeMaxDynamicSharedMemorySize,
                         GEMM_SMEM_BYTES);
    cudaFuncSetAttribute(tf32_gemm_kernel<false>,
                         cudaFuncAttributeMaxDynamicSharedMemorySize,
                         GEMM_SMEM_BYTES);

    // Preround GEMM inputs to tf32 (RNA); intermediates rounded in epilogues
    round_to_tf32(x,    xr,    (size_t)MTOT * DIMM);
    round_to_tf32(Wq,   wqr,   (size_t)DIMM * QCOLS);
    round_to_tf32(Wdkv, wdkvr, (size_t)DIMM * LATENT);
    round_to_tf32(Wkr,  wkrr,  (size_t)DIMM * DRP);
    round_to_tf32(Wukv, wukvr, (size_t)LATENT * KVCOLS);
    round_to_tf32(Wo,   wor,   (size_t)DIMM * DIMM);

    // Projections (tensor-core tf32; outputs rounded for downstream mma)
    tf32_gemm_kernel<true><<<dim3(QCOLS / GBN, MTOT / GBM), 256, GEMM_SMEM_BYTES>>>(
        xr, wqr, q, MTOT, QCOLS, DIMM);
    tf32_gemm_kernel<true><<<dim3(LATENT / GBN, MTOT / GBM), 256, GEMM_SMEM_BYTES>>>(
        xr, wdkvr, ckv, MTOT, LATENT, DIMM);
    tf32_gemm_kernel<true><<<dim3(1, MTOT / GBM), 256, GEMM_SMEM_BYTES>>>(
        xr, wkrr, kr, MTOT, DRP, DIMM);
    tf32_gemm_kernel<true><<<dim3(KVCOLS / GBN, MTOT / GBM), 256, GEMM_SMEM_BYTES>>>(
        ckv, wukvr, kv, MTOT, KVCOLS, LATENT);

    // RoPE (in place, outputs tf32-rounded)
    rope_q_kernel<<<(MTOT * NH * 32 + 255) / 256, 256>>>(q);
    rope_k_kernel<<<(MTOT * 32 + 255) / 256, 256>>>(kr);

    // Attention (tensor-core tf32, cp.async pipelined; output tf32-rounded)
    attn_kernel<<<dim3(SEQ / 64, NH, BATCH), 256, ATTN_SMEM_BYTES>>>(q, kv, kr, ao);

    // Output projection (fp32 output, no rounding)
    tf32_gemm_kernel<false><<<dim3(DIMM / GBN, MTOT / GBM), 256, GEMM_SMEM_BYTES>>>(
        ao, wor, out, MTOT, DIMM, DIMM);
}